// round 8
// baseline (speedup 1.0000x reference)
#include <cuda_runtime.h>
#include <cuda_bf16.h>
#include <math.h>
#include <stdint.h>

// Problem shape
#define BATCH 32
#define LDIM  512
#define DDIM  768
#define EPSF  1e-5f

#define TILES_D 6
#define NPAIRS  21                  // upper-triangular 128x128 tile pairs
#define BK      32                  // k per stage
#define NCHUNK  (LDIM / BK)         // 16
#define STAGES  3
#define OP_FLOATS   (128 * BK)      // 4096 floats = 16KB per operand tile
#define STAGE_FLOATS (2 * OP_FLOATS)
#define SMEM_BYTES  (STAGES * STAGE_FLOATS * 4)   // 98304

// Prep smem: 32 rows x 769 floats (odd pad -> conflict-free transpose) + 32 w's
#define PPAD 769
#define PREP_SMEM ((32 * PPAD + 32) * 4)          // 98560

// Scratch: transposed, weight-folded, tf32-rounded copy  Zt[b][d][l]
__device__ float g_Zt[BATCH * DDIM * LDIM];

__device__ __forceinline__ float to_tf32(float f) {
    uint32_t u;
    asm("cvt.rna.tf32.f32 %0, %1;" : "=r"(u) : "f"(f));
    return __uint_as_float(u);
}
__device__ __forceinline__ void cp16(uint32_t saddr, const void* g) {
    asm volatile("cp.async.cg.shared.global [%0], [%1], 16;" :: "r"(saddr), "l"(g));
}
__device__ __forceinline__ void ldsm4(uint32_t* r, uint32_t addr) {
    asm volatile("ldmatrix.sync.aligned.m8n8.x4.shared.b16 {%0,%1,%2,%3}, [%4];"
        : "=r"(r[0]), "=r"(r[1]), "=r"(r[2]), "=r"(r[3]) : "r"(addr));
}
__device__ __forceinline__ void mma_tf32(float* c, const uint32_t* a, uint32_t b0, uint32_t b1) {
    asm volatile(
        "mma.sync.aligned.m16n8k8.row.col.f32.tf32.tf32.f32 "
        "{%0,%1,%2,%3}, {%4,%5,%6,%7}, {%8,%9}, {%0,%1,%2,%3};"
        : "+f"(c[0]), "+f"(c[1]), "+f"(c[2]), "+f"(c[3])
        : "r"(a[0]), "r"(a[1]), "r"(a[2]), "r"(a[3]), "r"(b0), "r"(b1));
}

// ---------------------------------------------------------------------------
// Kernel 1 (fused prep): one pass over X.
// Per CTA: stage 32 token rows in smem, compute w per row, write
// Zt[b][d][l0..l0+31] = rna_tf32( sqrt(w[l]) * X[b][l][d] ), transposed.
// Store phase: lane owns l-quad li4 and one d-row -> 4 LDS + 1 STG.128.
// ---------------------------------------------------------------------------
extern __shared__ float psh[];

__global__ __launch_bounds__(256, 2)
void prep_kernel(const float* __restrict__ x) {
    float* wbuf = psh + 32 * PPAD;
    int b  = blockIdx.y;
    int l0 = blockIdx.x * 32;
    const float* __restrict__ Xb = x + ((size_t)b * LDIM + l0) * DDIM;
    int tid = threadIdx.x;
    int wid = tid >> 5, lane = tid & 31;

    // Load 32x768 floats (coalesced float4 LDG), scalar STS into padded rows
    #pragma unroll
    for (int i = 0; i < 24; i++) {
        int idx = tid + i * 256;            // 0..6143 float4 slots
        int row = idx / 192, c4 = idx % 192;
        float4 v = *(const float4*)(Xb + (size_t)row * DDIM + c4 * 4);
        float* d = psh + row * PPAD + c4 * 4;
        d[0] = v.x; d[1] = v.y; d[2] = v.z; d[3] = v.w;
    }
    __syncthreads();

    // Per-row sum of squares: warp wid handles rows 4*wid..4*wid+3
    #pragma unroll
    for (int r4 = 0; r4 < 4; r4++) {
        int r = wid * 4 + r4;
        const float* row = psh + r * PPAD;
        float s = 0.f;
        #pragma unroll
        for (int i = 0; i < 24; i++) {
            float v = row[lane + i * 32];
            s = fmaf(v, v, s);
        }
        #pragma unroll
        for (int o = 16; o > 0; o >>= 1) s += __shfl_xor_sync(0xffffffffu, s, o);
        if (lane == 0) wbuf[r] = sqrtf(sqrtf(EPSF + s));   // sqrt(w)
    }
    __syncthreads();

    // Transposed write: lane owns l-quad li4 = 4*(lane&7) and d-row offset lane>>3.
    // Warp-iter writes 4 consecutive d-rows x 32 l (4 x 128B fully coalesced).
    int li4 = (lane & 7) * 4;
    int dof = lane >> 3;
    float sw0 = wbuf[li4], sw1 = wbuf[li4 + 1], sw2 = wbuf[li4 + 2], sw3 = wbuf[li4 + 3];
    float* __restrict__ Zb = g_Zt + (size_t)b * DDIM * LDIM + l0;

    #pragma unroll 4
    for (int it = 0; it < 24; it++) {
        int dd = it * 32 + wid * 4 + dof;              // 0..767, disjoint cover
        float4 o4;
        o4.x = to_tf32(psh[(li4 + 0) * PPAD + dd] * sw0);
        o4.y = to_tf32(psh[(li4 + 1) * PPAD + dd] * sw1);
        o4.z = to_tf32(psh[(li4 + 2) * PPAD + dd] * sw2);
        o4.w = to_tf32(psh[(li4 + 3) * PPAD + dd] * sw3);
        *(float4*)(Zb + (size_t)dd * LDIM + li4) = o4;
    }
}

// ---------------------------------------------------------------------------
// Kernel 2: C tile = Zt_m Zt_n^T via tf32 mma.sync + ldmatrix + cp.async.
// Smem operand tile: 128 rows(d) x 32 floats(k), 16B units XOR-swizzled by row.
// (unchanged from R7 — verified correct & fastest so far)
// ---------------------------------------------------------------------------
extern __shared__ float smf[];

__global__ __launch_bounds__(256, 2)
void gram_tc_kernel(float* __restrict__ C) {
    int p = blockIdx.x % NPAIRS;
    int b = blockIdx.x / NPAIRS;
    int ti = 0, rem = p;
    while (rem >= TILES_D - ti) { rem -= TILES_D - ti; ti++; }
    int tj = ti + rem;
    int m0 = ti * 128, n0 = tj * 128;

    const float* __restrict__ Zb = g_Zt + (size_t)b * DDIM * LDIM;
    float* __restrict__ Cb = C + (size_t)b * DDIM * DDIM;

    int tid  = threadIdx.x;
    int wid  = tid >> 5, lane = tid & 31;
    int g = lane >> 2, t = lane & 3;
    int wm = (wid & 1) * 64;
    int wn = (wid >> 1) * 32;

    uint32_t sbase = (uint32_t)__cvta_generic_to_shared(smf);

    // cp.async slots: 1024 16B chunks per operand; 4 per thread per operand.
    const float* gAr[4]; const float* gBr[4]; int sdst[4];
    #pragma unroll
    for (int i = 0; i < 4; i++) {
        int j = tid + i * 256;
        int row = j >> 3, u = j & 7;
        gAr[i] = Zb + (size_t)(m0 + row) * LDIM + u * 4;
        gBr[i] = Zb + (size_t)(n0 + row) * LDIM + u * 4;
        sdst[i] = (row * BK + ((u ^ (row & 7)) * 4)) * 4;   // byte offset
    }

    auto ISSUE = [&](int chunk) {
        uint32_t base = sbase + (chunk % STAGES) * (STAGE_FLOATS * 4);
        int kc = chunk * BK;
        #pragma unroll
        for (int i = 0; i < 4; i++) {
            cp16(base + sdst[i],                   gAr[i] + kc);
            cp16(base + OP_FLOATS * 4 + sdst[i],   gBr[i] + kc);
        }
    };

    // ldmatrix row precompute
    int rowA[4], r7A[4];
    #pragma unroll
    for (int i = 0; i < 4; i++) {
        rowA[i] = wm + 16 * i + (lane & 7) + 8 * ((lane >> 3) & 1);
        r7A[i]  = rowA[i] & 7;
    }
    int uselA = lane >> 4;
    int rowB[2], r7B[2];
    #pragma unroll
    for (int jp = 0; jp < 2; jp++) {
        rowB[jp] = wn + 16 * jp + (lane & 7) + 8 * (lane >> 4);
        r7B[jp]  = rowB[jp] & 7;
    }
    int uselB = (lane >> 3) & 1;

    // Prologue
    #pragma unroll
    for (int c = 0; c < STAGES - 1; c++) {
        ISSUE(c);
        asm volatile("cp.async.commit_group;" ::: "memory");
    }

    float acc[4][4][4];
    #pragma unroll
    for (int i = 0; i < 4; i++)
        #pragma unroll
        for (int j = 0; j < 4; j++)
            #pragma unroll
            for (int r = 0; r < 4; r++) acc[i][j][r] = 0.f;

    for (int c = 0; c < NCHUNK; c++) {
        asm volatile("cp.async.wait_group %0;" :: "n"(STAGES - 2) : "memory");
        __syncthreads();

        // Issue next-stage loads FIRST so they overlap the MMA block below.
        if (c + STAGES - 1 < NCHUNK) ISSUE(c + STAGES - 1);
        asm volatile("cp.async.commit_group;" ::: "memory");

        uint32_t Ab = sbase + (c % STAGES) * (STAGE_FLOATS * 4);
        uint32_t Bb = Ab + OP_FLOATS * 4;

        #pragma unroll
        for (int kk = 0; kk < BK; kk += 8) {
            int ku = kk >> 2;
            uint32_t afr[4][4];
            #pragma unroll
            for (int i = 0; i < 4; i++)
                ldsm4(afr[i], Ab + rowA[i] * (BK * 4)
                               + (((ku + uselA) ^ r7A[i]) << 4));
            uint32_t bfr[2][4];
            #pragma unroll
            for (int jp = 0; jp < 2; jp++)
                ldsm4(bfr[jp], Bb + rowB[jp] * (BK * 4)
                                + (((ku + uselB) ^ r7B[jp]) << 4));
            #pragma unroll
            for (int i = 0; i < 4; i++)
                #pragma unroll
                for (int j = 0; j < 4; j++)
                    mma_tf32(acc[i][j], afr[i],
                             bfr[j >> 1][(j & 1) * 2], bfr[j >> 1][(j & 1) * 2 + 1]);
        }
    }

    // Epilogue: direct tile
    #pragma unroll
    for (int i = 0; i < 4; i++) {
        #pragma unroll
        for (int j = 0; j < 4; j++) {
            int m = m0 + wm + 16 * i + g;
            int n = n0 + wn + 8 * j + 2 * t;
            *(float2*)(Cb + (size_t)m * DDIM + n) =
                make_float2(acc[i][j][0], acc[i][j][1]);
            *(float2*)(Cb + (size_t)(m + 8) * DDIM + n) =
                make_float2(acc[i][j][2], acc[i][j][3]);
        }
    }
    // Mirror for off-diagonal tile pairs
    if (ti != tj) {
        #pragma unroll
        for (int i = 0; i < 4; i++) {
            #pragma unroll
            for (int j = 0; j < 4; j++) {
                int m = m0 + wm + 16 * i + g;
                int n = n0 + wn + 8 * j + 2 * t;
                Cb[(size_t)n * DDIM + m]           = acc[i][j][0];
                Cb[(size_t)(n + 1) * DDIM + m]     = acc[i][j][1];
                Cb[(size_t)n * DDIM + m + 8]       = acc[i][j][2];
                Cb[(size_t)(n + 1) * DDIM + m + 8] = acc[i][j][3];
            }
        }
    }
}

// ---------------------------------------------------------------------------
extern "C" void kernel_launch(void* const* d_in, const int* in_sizes, int n_in,
                              void* d_out, int out_size) {
    const float* x = (const float*)d_in[0];
    float* out = (float*)d_out;

    static int configured = 0;
    if (!configured) {
        cudaFuncSetAttribute(gram_tc_kernel,
                             cudaFuncAttributeMaxDynamicSharedMemorySize, SMEM_BYTES);
        cudaFuncSetAttribute(prep_kernel,
                             cudaFuncAttributeMaxDynamicSharedMemorySize, PREP_SMEM);
        configured = 1;
    }

    prep_kernel<<<dim3(LDIM / 32, BATCH), 256, PREP_SMEM>>>(x);
    gram_tc_kernel<<<BATCH * NPAIRS, 256, SMEM_BYTES>>>(out);
}

// round 9
// speedup vs baseline: 1.3152x; 1.3152x over previous
#include <cuda_runtime.h>
#include <cuda_fp16.h>
#include <math.h>
#include <stdint.h>

// Problem shape
#define BATCH 32
#define LDIM  512
#define DDIM  768
#define EPSF  1e-5f

#define TILES_D 6
#define NPAIRS  21                  // upper-triangular 128x128 tile pairs
#define BK      32                  // k (halfs) per stage
#define NCHUNK  (LDIM / BK)         // 16
#define STAGES  4
#define OP_BYTES    (128 * BK * 2)  // 8192 B per operand tile (64B rows)
#define STAGE_BYTES (2 * OP_BYTES)  // 16384
#define SMEM_BYTES  (STAGES * STAGE_BYTES)   // 65536

// Prep smem: 32 rows x 769 floats (odd pad) + 32 w's
#define PPAD 769
#define PREP_SMEM ((32 * PPAD + 32) * 4)

// Scratch: transposed, weight-folded, fp16 copy  Zh[b][d][l]  (24 MB)
__device__ __half g_Zh[BATCH * DDIM * LDIM];

__device__ __forceinline__ void cp16(uint32_t saddr, const void* g) {
    asm volatile("cp.async.cg.shared.global [%0], [%1], 16;" :: "r"(saddr), "l"(g));
}
__device__ __forceinline__ void ldsm4(uint32_t* r, uint32_t addr) {
    asm volatile("ldmatrix.sync.aligned.m8n8.x4.shared.b16 {%0,%1,%2,%3}, [%4];"
        : "=r"(r[0]), "=r"(r[1]), "=r"(r[2]), "=r"(r[3]) : "r"(addr));
}
__device__ __forceinline__ void mma_f16(float* c, const uint32_t* a, uint32_t b0, uint32_t b1) {
    asm volatile(
        "mma.sync.aligned.m16n8k16.row.col.f32.f16.f16.f32 "
        "{%0,%1,%2,%3}, {%4,%5,%6,%7}, {%8,%9}, {%0,%1,%2,%3};"
        : "+f"(c[0]), "+f"(c[1]), "+f"(c[2]), "+f"(c[3])
        : "r"(a[0]), "r"(a[1]), "r"(a[2]), "r"(a[3]), "r"(b0), "r"(b1));
}

// ---------------------------------------------------------------------------
// Kernel 1 (fused prep): one pass over X.
// Stage 32 token rows in smem, compute sqrt(w) per row, write transposed
// fp16 Zh[b][d][l0..l0+31] = half( sqrt(w[l]) * X[b][l][d] ).
// ---------------------------------------------------------------------------
extern __shared__ float psh[];

__global__ __launch_bounds__(256, 2)
void prep_kernel(const float* __restrict__ x) {
    float* wbuf = psh + 32 * PPAD;
    int b  = blockIdx.y;
    int l0 = blockIdx.x * 32;
    const float* __restrict__ Xb = x + ((size_t)b * LDIM + l0) * DDIM;
    int tid = threadIdx.x;
    int wid = tid >> 5, lane = tid & 31;

    // Load 32x768 floats (coalesced float4 LDG) into padded smem rows
    #pragma unroll
    for (int i = 0; i < 24; i++) {
        int idx = tid + i * 256;
        int row = idx / 192, c4 = idx % 192;
        float4 v = *(const float4*)(Xb + (size_t)row * DDIM + c4 * 4);
        float* d = psh + row * PPAD + c4 * 4;
        d[0] = v.x; d[1] = v.y; d[2] = v.z; d[3] = v.w;
    }
    __syncthreads();

    // Per-row sum of squares: warp wid handles rows 4*wid..4*wid+3
    #pragma unroll
    for (int r4 = 0; r4 < 4; r4++) {
        int r = wid * 4 + r4;
        const float* row = psh + r * PPAD;
        float s = 0.f;
        #pragma unroll
        for (int i = 0; i < 24; i++) {
            float v = row[lane + i * 32];
            s = fmaf(v, v, s);
        }
        #pragma unroll
        for (int o = 16; o > 0; o >>= 1) s += __shfl_xor_sync(0xffffffffu, s, o);
        if (lane == 0) wbuf[r] = sqrtf(sqrtf(EPSF + s));   // sqrt(w)
    }
    __syncthreads();

    // Transposed fp16 write: lane owns l-oct li8 = 8*(lane&3), d-row lane>>2.
    int li8 = (lane & 3) * 8;
    int dof = lane >> 2;
    float sw[8];
    #pragma unroll
    for (int q = 0; q < 8; q++) sw[q] = wbuf[li8 + q];
    __half* __restrict__ Zb = g_Zh + (size_t)b * DDIM * LDIM + l0;

    #pragma unroll 4
    for (int it = 0; it < 12; it++) {
        int dd = it * 64 + wid * 8 + dof;             // 0..767, disjoint cover
        __half2 h[4];
        #pragma unroll
        for (int q = 0; q < 4; q++) {
            float v0 = psh[(li8 + 2 * q)     * PPAD + dd] * sw[2 * q];
            float v1 = psh[(li8 + 2 * q + 1) * PPAD + dd] * sw[2 * q + 1];
            h[q] = __float22half2_rn(make_float2(v0, v1));
        }
        *(uint4*)(Zb + (size_t)dd * LDIM + li8) = *(uint4*)h;
    }
}

// ---------------------------------------------------------------------------
// Kernel 2: C tile = Zh_m Zh_n^T via fp16 mma m16n8k16 + ldmatrix + cp.async.
// Smem operand tile: 128 rows(d) x 32 halfs(k) = 64B rows, 4 x 16B units,
// swizzle unit' = u ^ ((row>>1)&3)  (all 8 rows of an ldmatrix phase distinct).
// ---------------------------------------------------------------------------
extern __shared__ char smc[];

__global__ __launch_bounds__(256, 2)
void gram_tc_kernel(float* __restrict__ C) {
    int p = blockIdx.x % NPAIRS;
    int b = blockIdx.x / NPAIRS;
    int ti = 0, rem = p;
    while (rem >= TILES_D - ti) { rem -= TILES_D - ti; ti++; }
    int tj = ti + rem;
    int m0 = ti * 128, n0 = tj * 128;

    const __half* __restrict__ Zb = g_Zh + (size_t)b * DDIM * LDIM;
    float* __restrict__ Cb = C + (size_t)b * DDIM * DDIM;

    int tid  = threadIdx.x;
    int wid  = tid >> 5, lane = tid & 31;
    int g = lane >> 2, t = lane & 3;
    int wm = (wid & 1) * 64;
    int wn = (wid >> 1) * 32;

    uint32_t sbase = (uint32_t)__cvta_generic_to_shared(smc);

    // cp.async slots: 512 16B chunks per operand; 2 per thread per operand.
    const __half* gAr[2]; const __half* gBr[2]; int sdst[2];
    #pragma unroll
    for (int i = 0; i < 2; i++) {
        int j = tid + i * 256;
        int row = j >> 2, u = j & 3;
        gAr[i] = Zb + (size_t)(m0 + row) * LDIM + u * 8;
        gBr[i] = Zb + (size_t)(n0 + row) * LDIM + u * 8;
        sdst[i] = row * 64 + ((u ^ ((row >> 1) & 3)) << 4);
    }

    auto ISSUE = [&](int chunk) {
        uint32_t base = sbase + (chunk % STAGES) * STAGE_BYTES;
        int kc = chunk * BK;
        #pragma unroll
        for (int i = 0; i < 2; i++) {
            cp16(base + sdst[i],            gAr[i] + kc);
            cp16(base + OP_BYTES + sdst[i], gBr[i] + kc);
        }
    };

    // ldmatrix row precompute (same lane algebra as tf32 version)
    int rowA[4], r3A[4];
    #pragma unroll
    for (int i = 0; i < 4; i++) {
        rowA[i] = wm + 16 * i + (lane & 7) + 8 * ((lane >> 3) & 1);
        r3A[i]  = (rowA[i] >> 1) & 3;
    }
    int uselA = lane >> 4;              // k16: lanes 16-31 take the next 16B unit
    int rowB[2], r3B[2];
    #pragma unroll
    for (int jp = 0; jp < 2; jp++) {
        rowB[jp] = wn + 16 * jp + (lane & 7) + 8 * (lane >> 4);
        r3B[jp]  = (rowB[jp] >> 1) & 3;
    }
    int uselB = (lane >> 3) & 1;

    // Prologue
    #pragma unroll
    for (int c = 0; c < STAGES - 1; c++) {
        ISSUE(c);
        asm volatile("cp.async.commit_group;" ::: "memory");
    }

    float acc[4][4][4];
    #pragma unroll
    for (int i = 0; i < 4; i++)
        #pragma unroll
        for (int j = 0; j < 4; j++)
            #pragma unroll
            for (int r = 0; r < 4; r++) acc[i][j][r] = 0.f;

    for (int c = 0; c < NCHUNK; c++) {
        asm volatile("cp.async.wait_group %0;" :: "n"(STAGES - 2) : "memory");
        __syncthreads();

        // Overlap next-stage loads with the MMA block below.
        if (c + STAGES - 1 < NCHUNK) ISSUE(c + STAGES - 1);
        asm volatile("cp.async.commit_group;" ::: "memory");

        uint32_t Ab = sbase + (c % STAGES) * STAGE_BYTES;
        uint32_t Bb = Ab + OP_BYTES;

        #pragma unroll
        for (int ks = 0; ks < 2; ks++) {          // two k16 steps per BK=32
            int ku = ks * 2;
            uint32_t afr[4][4];
            #pragma unroll
            for (int i = 0; i < 4; i++)
                ldsm4(afr[i], Ab + rowA[i] * 64
                               + (((ku + uselA) ^ r3A[i]) << 4));
            uint32_t bfr[2][4];
            #pragma unroll
            for (int jp = 0; jp < 2; jp++)
                ldsm4(bfr[jp], Bb + rowB[jp] * 64
                                + (((ku + uselB) ^ r3B[jp]) << 4));
            #pragma unroll
            for (int i = 0; i < 4; i++)
                #pragma unroll
                for (int j = 0; j < 4; j++)
                    mma_f16(acc[i][j], afr[i],
                            bfr[j >> 1][(j & 1) * 2], bfr[j >> 1][(j & 1) * 2 + 1]);
        }
    }

    // Epilogue: direct tile (fragment layout identical to tf32 m16n8k8)
    #pragma unroll
    for (int i = 0; i < 4; i++) {
        #pragma unroll
        for (int j = 0; j < 4; j++) {
            int m = m0 + wm + 16 * i + g;
            int n = n0 + wn + 8 * j + 2 * t;
            *(float2*)(Cb + (size_t)m * DDIM + n) =
                make_float2(acc[i][j][0], acc[i][j][1]);
            *(float2*)(Cb + (size_t)(m + 8) * DDIM + n) =
                make_float2(acc[i][j][2], acc[i][j][3]);
        }
    }
    // Mirror for off-diagonal tile pairs
    if (ti != tj) {
        #pragma unroll
        for (int i = 0; i < 4; i++) {
            #pragma unroll
            for (int j = 0; j < 4; j++) {
                int m = m0 + wm + 16 * i + g;
                int n = n0 + wn + 8 * j + 2 * t;
                Cb[(size_t)n * DDIM + m]           = acc[i][j][0];
                Cb[(size_t)(n + 1) * DDIM + m]     = acc[i][j][1];
                Cb[(size_t)n * DDIM + m + 8]       = acc[i][j][2];
                Cb[(size_t)(n + 1) * DDIM + m + 8] = acc[i][j][3];
            }
        }
    }
}

// ---------------------------------------------------------------------------
extern "C" void kernel_launch(void* const* d_in, const int* in_sizes, int n_in,
                              void* d_out, int out_size) {
    const float* x = (const float*)d_in[0];
    float* out = (float*)d_out;

    static int configured = 0;
    if (!configured) {
        cudaFuncSetAttribute(gram_tc_kernel,
                             cudaFuncAttributeMaxDynamicSharedMemorySize, SMEM_BYTES);
        cudaFuncSetAttribute(prep_kernel,
                             cudaFuncAttributeMaxDynamicSharedMemorySize, PREP_SMEM);
        configured = 1;
    }

    prep_kernel<<<dim3(LDIM / 32, BATCH), 256, PREP_SMEM>>>(x);
    gram_tc_kernel<<<BATCH * NPAIRS, 256, SMEM_BYTES>>>(out);
}

// round 10
// speedup vs baseline: 1.5150x; 1.1519x over previous
#include <cuda_runtime.h>
#include <cuda_fp16.h>
#include <math.h>
#include <stdint.h>

// Problem shape
#define BATCH 32
#define LDIM  512
#define DDIM  768
#define EPSF  1e-5f

// Gram tiling: 128(m) x 64(n) tiles on the 6x12 (128-row x 64-col) grid.
// Cover: tj >= 2*ti  -> 42 tiles per batch (same FLOPs as 21 symmetric 128x128).
#define NTILES  42
#define BK      64                   // k (halfs) per stage = 128B rows
#define NCHUNK  (LDIM / BK)          // 8
#define STAGES  3
#define A_BYTES (128 * BK * 2)       // 16384
#define B_BYTES (64  * BK * 2)       // 8192
#define STAGE_BYTES (A_BYTES + B_BYTES)          // 24576
#define SMEM_BYTES  (STAGES * STAGE_BYTES)       // 73728

// Prep smem: 32 rows x 769 floats (odd pad) + 32 w's
#define PPAD 769
#define PREP_SMEM ((32 * PPAD + 32) * 4)

// Scratch: transposed, weight-folded fp16 copy  Zh[b][d][l]  (24 MB)
__device__ __half g_Zh[BATCH * DDIM * LDIM];

__device__ __forceinline__ void cp16(uint32_t saddr, const void* g) {
    asm volatile("cp.async.cg.shared.global [%0], [%1], 16;" :: "r"(saddr), "l"(g));
}
__device__ __forceinline__ void ldsm4(uint32_t* r, uint32_t addr) {
    asm volatile("ldmatrix.sync.aligned.m8n8.x4.shared.b16 {%0,%1,%2,%3}, [%4];"
        : "=r"(r[0]), "=r"(r[1]), "=r"(r[2]), "=r"(r[3]) : "r"(addr));
}
__device__ __forceinline__ void mma_f16(float* c, const uint32_t* a, uint32_t b0, uint32_t b1) {
    asm volatile(
        "mma.sync.aligned.m16n8k16.row.col.f32.f16.f16.f32 "
        "{%0,%1,%2,%3}, {%4,%5,%6,%7}, {%8,%9}, {%0,%1,%2,%3};"
        : "+f"(c[0]), "+f"(c[1]), "+f"(c[2]), "+f"(c[3])
        : "r"(a[0]), "r"(a[1]), "r"(a[2]), "r"(a[3]), "r"(b0), "r"(b1));
}

// ---------------------------------------------------------------------------
// Kernel 1 (fused prep): one pass over X.
// Warp owns 4 token rows: load -> smem + in-register sum of squares (no
// re-read for the reduction), then transposed fp16 store of sqrt(w)*x.
// ---------------------------------------------------------------------------
extern __shared__ float psh[];

__global__ __launch_bounds__(256, 2)
void prep_kernel(const float* __restrict__ x) {
    float* wbuf = psh + 32 * PPAD;
    int b  = blockIdx.y;
    int l0 = blockIdx.x * 32;
    const float* __restrict__ Xb = x + ((size_t)b * LDIM + l0) * DDIM;
    int tid = threadIdx.x;
    int wid = tid >> 5, lane = tid & 31;

    // Load + reduce: warp wid handles rows 4*wid..4*wid+3
    #pragma unroll
    for (int rr = 0; rr < 4; rr++) {
        int r = wid * 4 + rr;
        const float4* Xr = (const float4*)(Xb + (size_t)r * DDIM);
        float* dr = psh + r * PPAD;
        float s = 0.f;
        #pragma unroll
        for (int i = 0; i < 6; i++) {
            float4 v = Xr[lane + i * 32];
            float* d = dr + (lane + i * 32) * 4;
            d[0] = v.x; d[1] = v.y; d[2] = v.z; d[3] = v.w;
            s = fmaf(v.x, v.x, s); s = fmaf(v.y, v.y, s);
            s = fmaf(v.z, v.z, s); s = fmaf(v.w, v.w, s);
        }
        #pragma unroll
        for (int o = 16; o > 0; o >>= 1) s += __shfl_xor_sync(0xffffffffu, s, o);
        if (lane == 0) wbuf[r] = sqrtf(sqrtf(EPSF + s));   // sqrt(w)
    }
    __syncthreads();

    // Transposed fp16 write: lane owns l-oct li8 = 8*(lane&3), d-row lane>>2.
    int li8 = (lane & 3) * 8;
    int dof = lane >> 2;
    float sw[8];
    #pragma unroll
    for (int q = 0; q < 8; q++) sw[q] = wbuf[li8 + q];
    __half* __restrict__ Zb = g_Zh + (size_t)b * DDIM * LDIM + l0;

    #pragma unroll 4
    for (int it = 0; it < 12; it++) {
        int dd = it * 64 + wid * 8 + dof;             // 0..767, disjoint cover
        __half2 h[4];
        #pragma unroll
        for (int q = 0; q < 4; q++) {
            float v0 = psh[(li8 + 2 * q)     * PPAD + dd] * sw[2 * q];
            float v1 = psh[(li8 + 2 * q + 1) * PPAD + dd] * sw[2 * q + 1];
            h[q] = __float22half2_rn(make_float2(v0, v1));
        }
        *(uint4*)(Zb + (size_t)dd * LDIM + li8) = *(uint4*)h;
    }
}

// ---------------------------------------------------------------------------
// Kernel 2: 128x64 C tile = Zh_m (128 rows) x Zh_n (64 rows)^T.
// 128 threads, 4 warps (2m x 2n), warp tile 64x32 (verified fragment algebra).
// BK=64 -> 128B smem rows, swizzle u ^ (row&7). Always mirror (duplicate
// writes on straddling tiles carry identical values -> deterministic).
// ---------------------------------------------------------------------------
extern __shared__ char smc[];

__global__ __launch_bounds__(128, 3)
void gram_tc_kernel(float* __restrict__ C) {
    int p = blockIdx.x % NTILES;
    int b = blockIdx.x / NTILES;
    int ti = 0, rem = p;
    while (rem >= 12 - 2 * ti) { rem -= 12 - 2 * ti; ti++; }
    int tj = 2 * ti + rem;                 // tj in [2*ti, 11]
    int m0 = ti * 128, n0 = tj * 64;

    const __half* __restrict__ Zb = g_Zh + (size_t)b * DDIM * LDIM;
    float* __restrict__ Cb = C + (size_t)b * DDIM * DDIM;

    int tid  = threadIdx.x;
    int wid  = tid >> 5, lane = tid & 31;
    int g = lane >> 2, t = lane & 3;
    int wm = (wid & 1) * 64;
    int wn = (wid >> 1) * 32;              // wid>>1 in {0,1}

    uint32_t sbase = (uint32_t)__cvta_generic_to_shared(smc);

    // cp.async: A 1024 16B chunks (8/thread), B 512 chunks (4/thread)
    const __half* gAr[8]; uint32_t sA[8];
    #pragma unroll
    for (int i = 0; i < 8; i++) {
        int j = tid + i * 128;
        int row = j >> 3, u = j & 7;
        gAr[i] = Zb + (size_t)(m0 + row) * LDIM + u * 8;
        sA[i]  = row * 128 + ((u ^ (row & 7)) << 4);
    }
    const __half* gBr[4]; uint32_t sB[4];
    #pragma unroll
    for (int i = 0; i < 4; i++) {
        int j = tid + i * 128;
        int row = j >> 3, u = j & 7;
        gBr[i] = Zb + (size_t)(n0 + row) * LDIM + u * 8;
        sB[i]  = row * 128 + ((u ^ (row & 7)) << 4);
    }

    auto ISSUE = [&](int chunk) {
        uint32_t base = sbase + (chunk % STAGES) * STAGE_BYTES;
        int kc = chunk * BK;
        #pragma unroll
        for (int i = 0; i < 8; i++) cp16(base + sA[i], gAr[i] + kc);
        #pragma unroll
        for (int i = 0; i < 4; i++) cp16(base + A_BYTES + sB[i], gBr[i] + kc);
    };

    // ldmatrix row precompute (same lane algebra as verified R7/R9 kernels)
    int rowA[4], r7A[4];
    #pragma unroll
    for (int i = 0; i < 4; i++) {
        rowA[i] = wm + 16 * i + (lane & 7) + 8 * ((lane >> 3) & 1);
        r7A[i]  = rowA[i] & 7;
    }
    int uselA = lane >> 4;
    int rowB[2], r7B[2];
    #pragma unroll
    for (int jp = 0; jp < 2; jp++) {
        rowB[jp] = wn + 16 * jp + (lane & 7) + 8 * (lane >> 4);
        r7B[jp]  = rowB[jp] & 7;
    }
    int uselB = (lane >> 3) & 1;

    // Prologue
    #pragma unroll
    for (int c = 0; c < STAGES - 1; c++) {
        ISSUE(c);
        asm volatile("cp.async.commit_group;" ::: "memory");
    }

    float acc[4][4][4];
    #pragma unroll
    for (int i = 0; i < 4; i++)
        #pragma unroll
        for (int j = 0; j < 4; j++)
            #pragma unroll
            for (int r = 0; r < 4; r++) acc[i][j][r] = 0.f;

    for (int c = 0; c < NCHUNK; c++) {
        asm volatile("cp.async.wait_group %0;" :: "n"(STAGES - 2) : "memory");
        __syncthreads();

        if (c + STAGES - 1 < NCHUNK) ISSUE(c + STAGES - 1);
        asm volatile("cp.async.commit_group;" ::: "memory");

        uint32_t Ab = sbase + (c % STAGES) * STAGE_BYTES;
        uint32_t Bb = Ab + A_BYTES;

        #pragma unroll
        for (int ks = 0; ks < 4; ks++) {          // four k16 steps per BK=64
            int ku = ks * 2;
            uint32_t afr[4][4];
            #pragma unroll
            for (int i = 0; i < 4; i++)
                ldsm4(afr[i], Ab + rowA[i] * 128
                               + (((ku + uselA) ^ r7A[i]) << 4));
            uint32_t bfr[2][4];
            #pragma unroll
            for (int jp = 0; jp < 2; jp++)
                ldsm4(bfr[jp], Bb + rowB[jp] * 128
                                + (((ku + uselB) ^ r7B[jp]) << 4));
            #pragma unroll
            for (int i = 0; i < 4; i++)
                #pragma unroll
                for (int j = 0; j < 4; j++)
                    mma_f16(acc[i][j], afr[i],
                            bfr[j >> 1][(j & 1) * 2], bfr[j >> 1][(j & 1) * 2 + 1]);
        }
    }

    // Epilogue: direct tile
    #pragma unroll
    for (int i = 0; i < 4; i++) {
        #pragma unroll
        for (int j = 0; j < 4; j++) {
            int m = m0 + wm + 16 * i + g;
            int n = n0 + wn + 8 * j + 2 * t;
            *(float2*)(Cb + (size_t)m * DDIM + n) =
                make_float2(acc[i][j][0], acc[i][j][1]);
            *(float2*)(Cb + (size_t)(m + 8) * DDIM + n) =
                make_float2(acc[i][j][2], acc[i][j][3]);
        }
    }
    // Mirror (always; overlapping writes carry identical values)
    #pragma unroll
    for (int i = 0; i < 4; i++) {
        #pragma unroll
        for (int j = 0; j < 4; j++) {
            int m = m0 + wm + 16 * i + g;
            int n = n0 + wn + 8 * j + 2 * t;
            Cb[(size_t)n * DDIM + m]           = acc[i][j][0];
            Cb[(size_t)(n + 1) * DDIM + m]     = acc[i][j][1];
            Cb[(size_t)n * DDIM + m + 8]       = acc[i][j][2];
            Cb[(size_t)(n + 1) * DDIM + m + 8] = acc[i][j][3];
        }
    }
}

// ---------------------------------------------------------------------------
extern "C" void kernel_launch(void* const* d_in, const int* in_sizes, int n_in,
                              void* d_out, int out_size) {
    const float* x = (const float*)d_in[0];
    float* out = (float*)d_out;

    static int configured = 0;
    if (!configured) {
        cudaFuncSetAttribute(gram_tc_kernel,
                             cudaFuncAttributeMaxDynamicSharedMemorySize, SMEM_BYTES);
        cudaFuncSetAttribute(prep_kernel,
                             cudaFuncAttributeMaxDynamicSharedMemorySize, PREP_SMEM);
        configured = 1;
    }

    prep_kernel<<<dim3(LDIM / 32, BATCH), 256, PREP_SMEM>>>(x);
    gram_tc_kernel<<<BATCH * NTILES, 128, SMEM_BYTES>>>(out);
}